// round 5
// baseline (speedup 1.0000x reference)
#include <cuda_runtime.h>

#define Bn   1024
#define Kseg 160
#define WS   12
#define NPJ  16             // padded j-dim for ysT (uniform stores)
#define G    36
#define DH   1024
#define TPAD 164            // Kseg + 4 prefetch pad
#define STR4 (Bn * WS)      // float4 stride between t slots

#define SCL1 1.442695040888963f   // log2(e)
#define SCL2 2.885390081777927f   // 2*log2(e)

// Scratch (static device globals — no allocation)
__device__ float4 g_gi[TPAD * Bn * WS];    // [t][b][j] = {-s1*r, -s1*z, -s2*n, 0} prescaled gates
__device__ float4 g_pegi4[Kseg * WS];      // [t][j] prescaled pe-gates
__device__ float  g_weff[Kseg * WS * WS];  // folded decoder W1@W2 per segment
__device__ float  g_beff[Kseg * WS];       // folded decoder bias
__device__ float  g_ysT[Bn * NPJ * Kseg];  // [b][j(16)][t]  GRU2 outputs (transposed, padded)

__device__ __forceinline__ float fex2(float x) {
    float y; asm("ex2.approx.f32 %0, %1;" : "=f"(y) : "f"(x)); return y;
}
__device__ __forceinline__ float frcp(float x) {
    float y; asm("rcp.approx.f32 %0, %1;" : "=f"(y) : "f"(x)); return y;
}

// ---------------------------------------------------------------------------
// Kernel 1: encoder relu(xb@enc_W+enc_b) and gi = xs@Wih^T + bih (+bhh r,z),
// written prescaled for EX2-based activations.
// ---------------------------------------------------------------------------
__global__ void __launch_bounds__(256) enc_gi_kernel(
        const float* __restrict__ x,
        const float* __restrict__ enc_W,
        const float* __restrict__ enc_b,
        const float* __restrict__ Wih,
        const float* __restrict__ bih,
        const float* __restrict__ bhh) {
    __shared__ float sg[256 * 37];          // pad 36->37: conflict-free STS
    int k = blockIdx.x >> 2;
    int bbase = (blockIdx.x & 3) << 8;
    int b = bbase + threadIdx.x;

    const float4* xr4 = (const float4*)(x + (size_t)b * 1920 + k * WS);
    float4 x0 = xr4[0], x1 = xr4[1], x2 = xr4[2];
    float xv[WS] = {x0.x, x0.y, x0.z, x0.w, x1.x, x1.y, x1.z, x1.w,
                    x2.x, x2.y, x2.z, x2.w};

    const float* ew = enc_W + k * (WS * WS);
    float xs[WS];
#pragma unroll
    for (int o = 0; o < WS; ++o) {
        float a = enc_b[k * WS + o];
#pragma unroll
        for (int i = 0; i < WS; ++i) a = fmaf(xv[i], ew[i * WS + o], a);
        xs[o] = fmaxf(a, 0.0f);
    }

    float* sgr = sg + threadIdx.x * 37;
#pragma unroll
    for (int g = 0; g < G; ++g) {
        float a = bih[g] + ((g < 24) ? bhh[g] : 0.0f);   // fold bhh_r, bhh_z
#pragma unroll
        for (int o = 0; o < WS; ++o) a = fmaf(xs[o], Wih[g * WS + o], a);
        sgr[g] = a;
    }
    __syncthreads();

    // write out as prescaled float4 {r,z,n,0}
    float4* dst = g_gi + ((size_t)k * Bn + bbase) * WS;
    for (int i = threadIdx.x; i < 256 * WS; i += 256) {
        int bl = i / WS;
        int j = i - bl * WS;
        const float* s = sg + bl * 37 + j;
        dst[i] = make_float4(-SCL1 * s[0], -SCL1 * s[12], -SCL2 * s[24], 0.0f);
    }
}

// ---------------------------------------------------------------------------
// Kernel 2: merged weff fold (blocks 0..159) + pegi table (block 160).
// ---------------------------------------------------------------------------
__global__ void __launch_bounds__(256) weff_pegi_kernel(
        const float* __restrict__ dec_W1,
        const float* __restrict__ dec_b1,
        const float* __restrict__ dec_W2,
        const float* __restrict__ dec_b2,
        const float* __restrict__ Wih) {
    if (blockIdx.x == Kseg) {
        // pegi: threads 0..159 each handle one k
        int k = threadIdx.x;
        if (k >= Kseg) return;
        float pe[WS];
        const float c = -9.210340371976184f / 12.0f;   // -ln(10000)/d
#pragma unroll
        for (int j = 0; j < 6; ++j) {
            float div = expf(c * (float)(2 * j));
            float ang = (float)k * div;
            pe[2 * j]     = sinf(ang);
            pe[2 * j + 1] = cosf(ang);
        }
        float ch = sinf((float)k);
#pragma unroll
        for (int o = 0; o < WS; ++o) pe[o] += ch;
        float pg[G];
#pragma unroll
        for (int g = 0; g < G; ++g) {
            float a = 0.0f;
#pragma unroll
            for (int o = 0; o < WS; ++o) a = fmaf(pe[o], Wih[g * WS + o], a);
            pg[g] = a;
        }
#pragma unroll
        for (int j = 0; j < WS; ++j)
            g_pegi4[k * WS + j] = make_float4(-SCL1 * pg[j], -SCL1 * pg[12 + j],
                                              -SCL2 * pg[24 + j], 0.0f);
        return;
    }

    __shared__ float w2s[DH * WS];   // 48 KB
    int k = blockIdx.x;
    const float4* W24 = (const float4*)(dec_W2 + (size_t)k * DH * WS);
    float4* w2s4 = (float4*)w2s;
    for (int i = threadIdx.x; i < DH * WS / 4; i += 256) w2s4[i] = W24[i];
    __syncthreads();

    int t = threadIdx.x;
    if (t < 144) {
        int d = t / WS, o = t - (t / WS) * WS;
        const float4* w14 = (const float4*)(dec_W1 + ((size_t)k * WS + d) * DH);
        float a0 = 0.f, a1 = 0.f, a2 = 0.f, a3 = 0.f;
        float a4 = 0.f, a5 = 0.f, a6 = 0.f, a7 = 0.f;
        for (int q = 0; q < DH / 4; q += 2) {
            float4 u = w14[q], v = w14[q + 1];
            int h = q * 4;
            a0 = fmaf(u.x, w2s[(h + 0) * WS + o], a0);
            a1 = fmaf(u.y, w2s[(h + 1) * WS + o], a1);
            a2 = fmaf(u.z, w2s[(h + 2) * WS + o], a2);
            a3 = fmaf(u.w, w2s[(h + 3) * WS + o], a3);
            a4 = fmaf(v.x, w2s[(h + 4) * WS + o], a4);
            a5 = fmaf(v.y, w2s[(h + 5) * WS + o], a5);
            a6 = fmaf(v.z, w2s[(h + 6) * WS + o], a6);
            a7 = fmaf(v.w, w2s[(h + 7) * WS + o], a7);
        }
        g_weff[k * 144 + d * WS + o] =
            ((a0 + a1) + (a2 + a3)) + ((a4 + a5) + (a6 + a7));
    } else if (t < 156) {
        int o = t - 144;
        const float4* b14 = (const float4*)(dec_b1 + (size_t)k * DH);
        float a0 = dec_b2[k * WS + o], a1 = 0.f, a2 = 0.f, a3 = 0.f;
        for (int q = 0; q < DH / 4; ++q) {
            float4 u = b14[q];
            int h = q * 4;
            a0 = fmaf(u.x, w2s[(h + 0) * WS + o], a0);
            a1 = fmaf(u.y, w2s[(h + 1) * WS + o], a1);
            a2 = fmaf(u.z, w2s[(h + 2) * WS + o], a2);
            a3 = fmaf(u.w, w2s[(h + 3) * WS + o], a3);
        }
        g_beff[k * WS + o] = (a0 + a1) + (a2 + a3);
    }
}

// ---------------------------------------------------------------------------
// Kernel 3: recurrence. One row per 16-lane group; h broadcast via smem
// (STS + syncwarp + 3x LDS.128 broadcast) instead of 12 shfls. Prescaled
// gates -> EX2/RCP activations. 4-deep rotating gi prefetch.
// ---------------------------------------------------------------------------
__device__ __forceinline__ float gstep2(float h, float gr, float gz, float gn,
                                        float bnp,
                                        const float wr[12], const float wz[12],
                                        const float wn[12],
                                        float4 u, float4 v, float4 w) {
    float hx[12] = {u.x, u.y, u.z, u.w, v.x, v.y, v.z, v.w, w.x, w.y, w.z, w.w};
    float a0 = gr, a1 = 0.f, b0 = gz, b1 = 0.f, c0 = bnp, c1 = 0.f;
#pragma unroll
    for (int i = 0; i < 12; i += 2) {
        a0 = fmaf(wr[i], hx[i], a0); a1 = fmaf(wr[i + 1], hx[i + 1], a1);
        b0 = fmaf(wz[i], hx[i], b0); b1 = fmaf(wz[i + 1], hx[i + 1], b1);
        c0 = fmaf(wn[i], hx[i], c0); c1 = fmaf(wn[i + 1], hx[i + 1], c1);
    }
    float r = frcp(1.0f + fex2(a0 + a1));              // sigmoid (prescaled)
    float z = frcp(1.0f + fex2(b0 + b1));
    float n = fmaf(2.0f, frcp(1.0f + fex2(fmaf(r, c0 + c1, gn))), -1.0f); // tanh
    return fmaf(z, h - n, n);
}

__global__ void __launch_bounds__(128) rnn_kernel(const float* __restrict__ Whh,
                                                  const float* __restrict__ bhh) {
    __shared__ float4 pegis[Kseg * WS];                 // 30 KB
    __shared__ __align__(16) float hbuf[2][8][16];      // double-buffered h
    int lane16 = threadIdx.x & 15;
    int grp = threadIdx.x >> 4;                         // 0..7
    int row = blockIdx.x * 8 + grp;                     // 0..1023
    int j = (lane16 < WS) ? lane16 : (WS - 1);

    float wr[12], wz[12], wn[12];
#pragma unroll
    for (int i = 0; i < 12; ++i) {
        wr[i] = -SCL1 * Whh[j * 12 + i];
        wz[i] = -SCL1 * Whh[(12 + j) * 12 + i];
        wn[i] = -SCL2 * Whh[(24 + j) * 12 + i];
    }
    float bnp = -SCL2 * bhh[24 + j];

    for (int i = threadIdx.x; i < Kseg * WS; i += 128) pegis[i] = g_pegi4[i];
    __syncthreads();

    const float4* pA = g_gi + (size_t)row * WS + j;
    float h = 0.0f;
    float4 a0, a1, a2, a3;
    const float4* q;
    float4 u, v, w;

#define BCAST(slot)                                                     \
    hbuf[slot][grp][lane16] = h;                                        \
    __syncwarp();                                                       \
    { const float4* _hb = (const float4*)hbuf[slot][grp];               \
      u = _hb[0]; v = _hb[1]; w = _hb[2]; }

    // ---------------- phase 1: first GRU (keep only final h) ---------------
    a0 = pA[0];
    a1 = pA[STR4];
    a2 = pA[2 * STR4];
    a3 = pA[3 * STR4];
    q = pA + 4 * STR4;
    for (int t = 0; t < Kseg; t += 4) {
        BCAST(0); h = gstep2(h, a0.x, a0.y, a0.z, bnp, wr, wz, wn, u, v, w);
        a0 = q[0];
        BCAST(1); h = gstep2(h, a1.x, a1.y, a1.z, bnp, wr, wz, wn, u, v, w);
        a1 = q[STR4];
        BCAST(0); h = gstep2(h, a2.x, a2.y, a2.z, bnp, wr, wz, wn, u, v, w);
        a2 = q[2 * STR4];
        BCAST(1); h = gstep2(h, a3.x, a3.y, a3.z, bnp, wr, wz, wn, u, v, w);
        a3 = q[3 * STR4];
        q += 4 * STR4;
    }

    // ---------------- phase 2: second GRU (emit all outputs) ---------------
    float* yA = g_ysT + ((size_t)row * NPJ + lane16) * Kseg;   // padded: all lanes store
    a0 = pA[0];
    a1 = pA[STR4];
    a2 = pA[2 * STR4];
    a3 = pA[3 * STR4];
    q = pA + 4 * STR4;
    const float4* pg = pegis + j;
    for (int t = 0; t < Kseg; t += 4) {
        float4 p0 = pg[0], p1 = pg[WS], p2 = pg[2 * WS], p3 = pg[3 * WS];
        pg += 4 * WS;
        float4 ya;
        BCAST(0);
        h = gstep2(h, a0.x + p0.x, a0.y + p0.y, a0.z + p0.z, bnp, wr, wz, wn, u, v, w);
        ya.x = h;  a0 = q[0];
        BCAST(1);
        h = gstep2(h, a1.x + p1.x, a1.y + p1.y, a1.z + p1.z, bnp, wr, wz, wn, u, v, w);
        ya.y = h;  a1 = q[STR4];
        BCAST(0);
        h = gstep2(h, a2.x + p2.x, a2.y + p2.y, a2.z + p2.z, bnp, wr, wz, wn, u, v, w);
        ya.z = h;  a2 = q[2 * STR4];
        BCAST(1);
        h = gstep2(h, a3.x + p3.x, a3.y + p3.y, a3.z + p3.z, bnp, wr, wz, wn, u, v, w);
        ya.w = h;  a3 = q[3 * STR4];
        q += 4 * STR4;
        *(float4*)(yA + t) = ya;                        // uniform store, no branch
    }
#undef BCAST
}

// ---------------------------------------------------------------------------
// Kernel 4: folded decoder: out[b,k,:] = ysT[b,:,k] @ Weff[k] + beff[k]
// ---------------------------------------------------------------------------
__global__ void __launch_bounds__(256) dec_kernel(float* __restrict__ out) {
    int tid = blockIdx.x * blockDim.x + threadIdx.x;
    int b = tid / Kseg;
    int k = tid - b * Kseg;
    if (b >= Bn) return;

    const float* yb = g_ysT + (size_t)b * NPJ * Kseg + k;
    float hv[WS];
#pragma unroll
    for (int d = 0; d < WS; ++d) hv[d] = yb[d * Kseg];

    const float4* be4 = (const float4*)(g_beff + k * WS);
    float4 b0 = be4[0], b1 = be4[1], b2 = be4[2];
    float acc[WS] = {b0.x, b0.y, b0.z, b0.w, b1.x, b1.y, b1.z, b1.w,
                     b2.x, b2.y, b2.z, b2.w};

    const float4* w4 = (const float4*)(g_weff + k * 144);
#pragma unroll
    for (int d = 0; d < WS; ++d) {
        float4 wa = w4[d * 3 + 0], wb = w4[d * 3 + 1], wc = w4[d * 3 + 2];
        float hd = hv[d];
        acc[0] = fmaf(hd, wa.x, acc[0]); acc[1] = fmaf(hd, wa.y, acc[1]);
        acc[2] = fmaf(hd, wa.z, acc[2]); acc[3] = fmaf(hd, wa.w, acc[3]);
        acc[4] = fmaf(hd, wb.x, acc[4]); acc[5] = fmaf(hd, wb.y, acc[5]);
        acc[6] = fmaf(hd, wb.z, acc[6]); acc[7] = fmaf(hd, wb.w, acc[7]);
        acc[8] = fmaf(hd, wc.x, acc[8]); acc[9] = fmaf(hd, wc.y, acc[9]);
        acc[10] = fmaf(hd, wc.z, acc[10]); acc[11] = fmaf(hd, wc.w, acc[11]);
    }

    float4* op4 = (float4*)(out + (size_t)b * 1920 + k * WS);
    op4[0] = make_float4(acc[0], acc[1], acc[2], acc[3]);
    op4[1] = make_float4(acc[4], acc[5], acc[6], acc[7]);
    op4[2] = make_float4(acc[8], acc[9], acc[10], acc[11]);
}

// ---------------------------------------------------------------------------
extern "C" void kernel_launch(void* const* d_in, const int* in_sizes, int n_in,
                              void* d_out, int out_size) {
    const float* x     = (const float*)d_in[0];
    const float* enc_W = (const float*)d_in[1];
    const float* enc_b = (const float*)d_in[2];
    const float* Wih   = (const float*)d_in[3];
    const float* Whh   = (const float*)d_in[4];
    const float* bih   = (const float*)d_in[5];
    const float* bhh   = (const float*)d_in[6];
    const float* dW1   = (const float*)d_in[7];
    const float* db1   = (const float*)d_in[8];
    const float* dW2   = (const float*)d_in[9];
    const float* db2   = (const float*)d_in[10];
    float* out = (float*)d_out;

    enc_gi_kernel<<<640, 256>>>(x, enc_W, enc_b, Wih, bih, bhh);
    weff_pegi_kernel<<<Kseg + 1, 256>>>(dW1, db1, dW2, db2, Wih);
    rnn_kernel<<<128, 128>>>(Whh, bhh);      // 1024 rows, one per 16-lane group
    dec_kernel<<<640, 256>>>(out);
}

// round 6
// speedup vs baseline: 1.1954x; 1.1954x over previous
#include <cuda_runtime.h>

#define Bn   1024
#define Kseg 160
#define WS   12
#define G    36
#define DH   1024
#define TPAD 164            // Kseg + 4 prefetch pad
#define STR4 (Bn * WS)      // float4 stride between t slots

#define SCL1 1.442695040888963f   // log2(e)
#define SCL2 2.885390081777927f   // 2*log2(e)

// Scratch (static device globals — no allocation)
__device__ float4 g_gi[TPAD * Bn * WS];    // [t][b][j] = prescaled {r,z,n,0} gates
__device__ float4 g_pegi4[Kseg * WS];      // [t][j] prescaled pe-gates
__device__ float4 g_wdec[Kseg * WS * 4];   // [k][j][4]: {w0..3},{w4..7},{w8..11},{beff,-,-,-}
                                           // w_d = weff[k][d][j] (transposed for lane-j use)

__device__ __forceinline__ float fex2(float x) {
    float y; asm("ex2.approx.f32 %0, %1;" : "=f"(y) : "f"(x)); return y;
}
__device__ __forceinline__ float frcp(float x) {
    float y; asm("rcp.approx.f32 %0, %1;" : "=f"(y) : "f"(x)); return y;
}

// ---------------------------------------------------------------------------
// Kernel 1: encoder relu(xb@enc_W+enc_b) and gi = xs@Wih^T + bih (+bhh r,z),
// written prescaled for EX2-based activations.
// ---------------------------------------------------------------------------
__global__ void __launch_bounds__(256) enc_gi_kernel(
        const float* __restrict__ x,
        const float* __restrict__ enc_W,
        const float* __restrict__ enc_b,
        const float* __restrict__ Wih,
        const float* __restrict__ bih,
        const float* __restrict__ bhh) {
    __shared__ float sg[256 * 37];          // pad 36->37: conflict-free STS
    int k = blockIdx.x >> 2;
    int bbase = (blockIdx.x & 3) << 8;
    int b = bbase + threadIdx.x;

    const float4* xr4 = (const float4*)(x + (size_t)b * 1920 + k * WS);
    float4 x0 = xr4[0], x1 = xr4[1], x2 = xr4[2];
    float xv[WS] = {x0.x, x0.y, x0.z, x0.w, x1.x, x1.y, x1.z, x1.w,
                    x2.x, x2.y, x2.z, x2.w};

    const float* ew = enc_W + k * (WS * WS);
    float xs[WS];
#pragma unroll
    for (int o = 0; o < WS; ++o) {
        float a = enc_b[k * WS + o];
#pragma unroll
        for (int i = 0; i < WS; ++i) a = fmaf(xv[i], ew[i * WS + o], a);
        xs[o] = fmaxf(a, 0.0f);
    }

    float* sgr = sg + threadIdx.x * 37;
#pragma unroll
    for (int g = 0; g < G; ++g) {
        float a = bih[g] + ((g < 24) ? bhh[g] : 0.0f);   // fold bhh_r, bhh_z
#pragma unroll
        for (int o = 0; o < WS; ++o) a = fmaf(xs[o], Wih[g * WS + o], a);
        sgr[g] = a;
    }
    __syncthreads();

    // write out as prescaled float4 {r,z,n,0}
    float4* dst = g_gi + ((size_t)k * Bn + bbase) * WS;
    for (int i = threadIdx.x; i < 256 * WS; i += 256) {
        int bl = i / WS;
        int j = i - bl * WS;
        const float* s = sg + bl * 37 + j;
        dst[i] = make_float4(-SCL1 * s[0], -SCL1 * s[12], -SCL2 * s[24], 0.0f);
    }
}

// ---------------------------------------------------------------------------
// Kernel 2: merged weff fold (blocks 0..159, transposed output) + pegi
// table (block 160).
// ---------------------------------------------------------------------------
__global__ void __launch_bounds__(256) weff_pegi_kernel(
        const float* __restrict__ dec_W1,
        const float* __restrict__ dec_b1,
        const float* __restrict__ dec_W2,
        const float* __restrict__ dec_b2,
        const float* __restrict__ Wih) {
    if (blockIdx.x == Kseg) {
        int k = threadIdx.x;
        if (k >= Kseg) return;
        float pe[WS];
        const float c = -9.210340371976184f / 12.0f;   // -ln(10000)/d
#pragma unroll
        for (int j = 0; j < 6; ++j) {
            float div = expf(c * (float)(2 * j));
            float ang = (float)k * div;
            pe[2 * j]     = sinf(ang);
            pe[2 * j + 1] = cosf(ang);
        }
        float ch = sinf((float)k);
#pragma unroll
        for (int o = 0; o < WS; ++o) pe[o] += ch;
        float pg[G];
#pragma unroll
        for (int g = 0; g < G; ++g) {
            float a = 0.0f;
#pragma unroll
            for (int o = 0; o < WS; ++o) a = fmaf(pe[o], Wih[g * WS + o], a);
            pg[g] = a;
        }
#pragma unroll
        for (int j = 0; j < WS; ++j)
            g_pegi4[k * WS + j] = make_float4(-SCL1 * pg[j], -SCL1 * pg[12 + j],
                                              -SCL2 * pg[24 + j], 0.0f);
        return;
    }

    __shared__ float w2s[DH * WS];   // 48 KB
    int k = blockIdx.x;
    const float4* W24 = (const float4*)(dec_W2 + (size_t)k * DH * WS);
    float4* w2s4 = (float4*)w2s;
    for (int i = threadIdx.x; i < DH * WS / 4; i += 256) w2s4[i] = W24[i];
    __syncthreads();

    float* wdecF = (float*)g_wdec;        // [k][j][16] floats
    int t = threadIdx.x;
    if (t < 144) {
        int d = t / WS, o = t - (t / WS) * WS;
        const float4* w14 = (const float4*)(dec_W1 + ((size_t)k * WS + d) * DH);
        float a0 = 0.f, a1 = 0.f, a2 = 0.f, a3 = 0.f;
        float a4 = 0.f, a5 = 0.f, a6 = 0.f, a7 = 0.f;
        for (int q = 0; q < DH / 4; q += 2) {
            float4 u = w14[q], v = w14[q + 1];
            int h = q * 4;
            a0 = fmaf(u.x, w2s[(h + 0) * WS + o], a0);
            a1 = fmaf(u.y, w2s[(h + 1) * WS + o], a1);
            a2 = fmaf(u.z, w2s[(h + 2) * WS + o], a2);
            a3 = fmaf(u.w, w2s[(h + 3) * WS + o], a3);
            a4 = fmaf(v.x, w2s[(h + 4) * WS + o], a4);
            a5 = fmaf(v.y, w2s[(h + 5) * WS + o], a5);
            a6 = fmaf(v.z, w2s[(h + 6) * WS + o], a6);
            a7 = fmaf(v.w, w2s[(h + 7) * WS + o], a7);
        }
        // transposed: row = (k, out=o), element d
        wdecF[((size_t)k * WS + o) * 16 + d] =
            ((a0 + a1) + (a2 + a3)) + ((a4 + a5) + (a6 + a7));
    } else if (t < 156) {
        int o = t - 144;
        const float4* b14 = (const float4*)(dec_b1 + (size_t)k * DH);
        float a0 = dec_b2[k * WS + o], a1 = 0.f, a2 = 0.f, a3 = 0.f;
        for (int q = 0; q < DH / 4; ++q) {
            float4 u = b14[q];
            int h = q * 4;
            a0 = fmaf(u.x, w2s[(h + 0) * WS + o], a0);
            a1 = fmaf(u.y, w2s[(h + 1) * WS + o], a1);
            a2 = fmaf(u.z, w2s[(h + 2) * WS + o], a2);
            a3 = fmaf(u.w, w2s[(h + 3) * WS + o], a3);
        }
        wdecF[((size_t)k * WS + o) * 16 + 12] = (a0 + a1) + (a2 + a3);
    }
}

// ---------------------------------------------------------------------------
// Kernel 3: recurrence + fused decoder. One row per 16-lane group (shfl
// broadcast). Prescaled EX2/RCP activations. gi: 4-deep rotating prefetch.
// Phase 2: the shfl'd h of step t (= ys[t-1]) also feeds 12 decoder FMAs
// producing out[b, (t-1)*12 + j] directly — no ys buffer, no dec kernel.
// ---------------------------------------------------------------------------
__device__ __forceinline__ void bcast(float h, float* hx) {
#pragma unroll
    for (int i = 0; i < 12; ++i) hx[i] = __shfl_sync(0xffffffffu, h, i, 16);
}

__device__ __forceinline__ float gates(const float* hx, float gr, float gz,
                                       float gn, float bnp,
                                       const float* wr, const float* wz,
                                       const float* wn, float h) {
    float a0 = gr, a1 = 0.f, b0 = gz, b1 = 0.f, c0 = bnp, c1 = 0.f;
#pragma unroll
    for (int i = 0; i < 12; i += 2) {
        a0 = fmaf(wr[i], hx[i], a0); a1 = fmaf(wr[i + 1], hx[i + 1], a1);
        b0 = fmaf(wz[i], hx[i], b0); b1 = fmaf(wz[i + 1], hx[i + 1], b1);
        c0 = fmaf(wn[i], hx[i], c0); c1 = fmaf(wn[i + 1], hx[i + 1], c1);
    }
    float r = frcp(1.0f + fex2(a0 + a1));              // sigmoid (prescaled)
    float z = frcp(1.0f + fex2(b0 + b1));
    float n = fmaf(2.0f, frcp(1.0f + fex2(fmaf(r, c0 + c1, gn))), -1.0f);
    return fmaf(z, h - n, n);
}

__device__ __forceinline__ float decacc(const float* hx, float4 w0, float4 w1,
                                        float4 w2, float be) {
    float s0 = be, s1 = 0.f, s2 = 0.f, s3 = 0.f;
    s0 = fmaf(hx[0], w0.x, s0); s1 = fmaf(hx[1], w0.y, s1);
    s2 = fmaf(hx[2], w0.z, s2); s3 = fmaf(hx[3], w0.w, s3);
    s0 = fmaf(hx[4], w1.x, s0); s1 = fmaf(hx[5], w1.y, s1);
    s2 = fmaf(hx[6], w1.z, s2); s3 = fmaf(hx[7], w1.w, s3);
    s0 = fmaf(hx[8], w2.x, s0); s1 = fmaf(hx[9], w2.y, s1);
    s2 = fmaf(hx[10], w2.z, s2); s3 = fmaf(hx[11], w2.w, s3);
    return (s0 + s1) + (s2 + s3);
}

__global__ void __launch_bounds__(128) rnn_kernel(const float* __restrict__ Whh,
                                                  const float* __restrict__ bhh,
                                                  float* __restrict__ out) {
    __shared__ float4 pegis[Kseg * WS];   // 30 KB
    int lane16 = threadIdx.x & 15;
    int row = blockIdx.x * 8 + (threadIdx.x >> 4);   // 0..1023
    bool act = (lane16 < WS);
    int j = act ? lane16 : (WS - 1);

    float wr[12], wz[12], wn[12];
#pragma unroll
    for (int i = 0; i < 12; ++i) {
        wr[i] = -SCL1 * Whh[j * 12 + i];
        wz[i] = -SCL1 * Whh[(12 + j) * 12 + i];
        wn[i] = -SCL2 * Whh[(24 + j) * 12 + i];
    }
    float bnp = -SCL2 * bhh[24 + j];

    for (int i = threadIdx.x; i < Kseg * WS; i += 128) pegis[i] = g_pegi4[i];
    __syncthreads();

    const float4* pA = g_gi + (size_t)row * WS + j;
    float h = 0.0f;
    float4 a0, a1, a2, a3;
    const float4* q;

    // ---------------- phase 1: first GRU (keep only final h) ---------------
    a0 = pA[0];
    a1 = pA[STR4];
    a2 = pA[2 * STR4];
    a3 = pA[3 * STR4];
    q = pA + 4 * STR4;
    for (int t = 0; t < Kseg; t += 4) {
        float hx[12];
        bcast(h, hx); h = gates(hx, a0.x, a0.y, a0.z, bnp, wr, wz, wn, h);
        a0 = q[0];
        bcast(h, hx); h = gates(hx, a1.x, a1.y, a1.z, bnp, wr, wz, wn, h);
        a1 = q[STR4];
        bcast(h, hx); h = gates(hx, a2.x, a2.y, a2.z, bnp, wr, wz, wn, h);
        a2 = q[2 * STR4];
        bcast(h, hx); h = gates(hx, a3.x, a3.y, a3.z, bnp, wr, wz, wn, h);
        a3 = q[3 * STR4];
        q += 4 * STR4;
    }

    // ---------------- phase 2: second GRU + fused decoder -------------------
    float* outp = out + (size_t)row * 1920 + j;
    const float4* wdb = g_wdec + (size_t)j * 4;   // + t*48 per step
    float4 wp0 = make_float4(0, 0, 0, 0), wp1 = wp0, wp2 = wp0, wp3 = wp0;

    a0 = pA[0];
    a1 = pA[STR4];
    a2 = pA[2 * STR4];
    a3 = pA[3 * STR4];
    q = pA + 4 * STR4;
    const float4* pg = pegis + j;

#define STEP2(AREG, PV, TT, QOFF)                                           \
    {                                                                       \
        float hx[12];                                                       \
        bcast(h, hx);                                                       \
        float oa = decacc(hx, wp0, wp1, wp2, wp3.x);                        \
        if (act && (TT) > 0) outp[((TT) - 1) * 12] = oa;                    \
        h = gates(hx, AREG.x + PV.x, AREG.y + PV.y, AREG.z + PV.z, bnp,     \
                  wr, wz, wn, h);                                           \
        AREG = q[QOFF];                                                     \
        const float4* _wb = wdb + (size_t)(TT) * 48;                        \
        wp0 = _wb[0]; wp1 = _wb[1]; wp2 = _wb[2]; wp3 = _wb[3];             \
    }

    for (int t = 0; t < Kseg; t += 4) {
        float4 p0 = pg[0], p1 = pg[WS], p2 = pg[2 * WS], p3 = pg[3 * WS];
        pg += 4 * WS;
        STEP2(a0, p0, t + 0, 0);
        STEP2(a1, p1, t + 1, STR4);
        STEP2(a2, p2, t + 2, 2 * STR4);
        STEP2(a3, p3, t + 3, 3 * STR4);
        q += 4 * STR4;
    }
#undef STEP2

    // tail: out for t = Kseg-1 (weights wdec[159] already in wp)
    {
        float hx[12];
        bcast(h, hx);
        float oa = decacc(hx, wp0, wp1, wp2, wp3.x);
        if (act) outp[(Kseg - 1) * 12] = oa;
    }
}

// ---------------------------------------------------------------------------
extern "C" void kernel_launch(void* const* d_in, const int* in_sizes, int n_in,
                              void* d_out, int out_size) {
    const float* x     = (const float*)d_in[0];
    const float* enc_W = (const float*)d_in[1];
    const float* enc_b = (const float*)d_in[2];
    const float* Wih   = (const float*)d_in[3];
    const float* Whh   = (const float*)d_in[4];
    const float* bih   = (const float*)d_in[5];
    const float* bhh   = (const float*)d_in[6];
    const float* dW1   = (const float*)d_in[7];
    const float* db1   = (const float*)d_in[8];
    const float* dW2   = (const float*)d_in[9];
    const float* db2   = (const float*)d_in[10];
    float* out = (float*)d_out;

    enc_gi_kernel<<<640, 256>>>(x, enc_W, enc_b, Wih, bih, bhh);
    weff_pegi_kernel<<<Kseg + 1, 256>>>(dW1, db1, dW2, db2, Wih);
    rnn_kernel<<<128, 128>>>(Whh, bhh, out);   // fused decoder output
}

// round 8
// speedup vs baseline: 1.6797x; 1.4051x over previous
#include <cuda_runtime.h>

#define Bn   1024
#define Kseg 160
#define WS   12
#define G    36
#define DH   1024
#define TPAD 164            // Kseg + 4 prefetch pad
#define STR4 (Bn * WS)      // float4 stride between t slots

#define SCL1 1.442695040888963f   // log2(e)
#define SCL2 2.885390081777927f   // 2*log2(e)

// Scratch (static device globals — no allocation)
__device__ float4 g_gi[TPAD * Bn * WS];    // [t][b][j] = prescaled {r,z,n,0} gates
__device__ float4 g_pegi4[Kseg * WS];      // [t][j] prescaled pe-gates
__device__ float4 g_wdec[Kseg * WS * 4];   // [k][j][4]: {w0..3},{w4..7},{w8..11},{beff,-,-,-}

__device__ __forceinline__ float fex2(float x) {
    float y; asm("ex2.approx.f32 %0, %1;" : "=f"(y) : "f"(x)); return y;
}
__device__ __forceinline__ float frcp(float x) {
    float y; asm("rcp.approx.f32 %0, %1;" : "=f"(y) : "f"(x)); return y;
}

// ---------------------------------------------------------------------------
// Kernel 1: encoder relu(xb@enc_W+enc_b) and gi = xs@Wih^T + bias (folded),
// prescaled for EX2 activations. All weight operands staged in smem
// (FIXED: strided staging loops cover all 432 Wih elements).
// ---------------------------------------------------------------------------
__global__ void __launch_bounds__(256) enc_gi_kernel(
        const float* __restrict__ x,
        const float* __restrict__ enc_W,
        const float* __restrict__ enc_b,
        const float* __restrict__ Wih,
        const float* __restrict__ bih,
        const float* __restrict__ bhh) {
    __shared__ float sWih[G * WS];      // 432
    __shared__ float sEW[WS * WS];      // 144
    __shared__ float sEB[WS];           // 12
    __shared__ float sBI[G];            // folded bias
    __shared__ float sg[256 * 37];      // pad 36->37: conflict-free
    int k = blockIdx.x >> 2;
    int bbase = (blockIdx.x & 3) << 8;
    int b = bbase + threadIdx.x;

    for (int t = threadIdx.x; t < G * WS; t += 256) sWih[t] = Wih[t];
    {
        int t = threadIdx.x;
        if (t < WS * WS) sEW[t] = enc_W[k * (WS * WS) + t];
        if (t < WS) sEB[t] = enc_b[k * WS + t];
        if (t < G) sBI[t] = bih[t] + ((t < 24) ? bhh[t] : 0.0f);
    }
    __syncthreads();

    const float4* xr4 = (const float4*)(x + (size_t)b * 1920 + k * WS);
    float4 x0 = xr4[0], x1 = xr4[1], x2 = xr4[2];
    float xv[WS] = {x0.x, x0.y, x0.z, x0.w, x1.x, x1.y, x1.z, x1.w,
                    x2.x, x2.y, x2.z, x2.w};

    float xs[WS];
#pragma unroll
    for (int o = 0; o < WS; ++o) {
        float a = sEB[o];
#pragma unroll
        for (int i = 0; i < WS; ++i) a = fmaf(xv[i], sEW[i * WS + o], a);
        xs[o] = fmaxf(a, 0.0f);
    }

    float* sgr = sg + threadIdx.x * 37;
#pragma unroll
    for (int g = 0; g < G; ++g) {
        float a = sBI[g];
#pragma unroll
        for (int o = 0; o < WS; ++o) a = fmaf(xs[o], sWih[g * WS + o], a);
        sgr[g] = a;
    }
    __syncthreads();

    // coalesced write-out as prescaled float4 {r,z,n,0}
    float4* dst = g_gi + ((size_t)k * Bn + bbase) * WS;
    for (int i = threadIdx.x; i < 256 * WS; i += 256) {
        int bl = i / WS;
        int j = i - bl * WS;
        const float* s = sg + bl * 37 + j;
        dst[i] = make_float4(-SCL1 * s[0], -SCL1 * s[12], -SCL2 * s[24], 0.0f);
    }
}

// ---------------------------------------------------------------------------
// Kernel 2: merged weff fold (blocks 0..159, transposed output) + pegi
// table (block 160).
// ---------------------------------------------------------------------------
__global__ void __launch_bounds__(256) weff_pegi_kernel(
        const float* __restrict__ dec_W1,
        const float* __restrict__ dec_b1,
        const float* __restrict__ dec_W2,
        const float* __restrict__ dec_b2,
        const float* __restrict__ Wih) {
    if (blockIdx.x == Kseg) {
        int k = threadIdx.x;
        if (k >= Kseg) return;
        float pe[WS];
        const float c = -9.210340371976184f / 12.0f;   // -ln(10000)/d
#pragma unroll
        for (int j = 0; j < 6; ++j) {
            float div = expf(c * (float)(2 * j));
            float ang = (float)k * div;
            pe[2 * j]     = sinf(ang);
            pe[2 * j + 1] = cosf(ang);
        }
        float ch = sinf((float)k);
#pragma unroll
        for (int o = 0; o < WS; ++o) pe[o] += ch;
        float pg[G];
#pragma unroll
        for (int g = 0; g < G; ++g) {
            float a = 0.0f;
#pragma unroll
            for (int o = 0; o < WS; ++o) a = fmaf(pe[o], Wih[g * WS + o], a);
            pg[g] = a;
        }
#pragma unroll
        for (int j = 0; j < WS; ++j)
            g_pegi4[k * WS + j] = make_float4(-SCL1 * pg[j], -SCL1 * pg[12 + j],
                                              -SCL2 * pg[24 + j], 0.0f);
        return;
    }

    __shared__ float w2s[DH * WS];   // 48 KB
    int k = blockIdx.x;
    const float4* W24 = (const float4*)(dec_W2 + (size_t)k * DH * WS);
    float4* w2s4 = (float4*)w2s;
    for (int i = threadIdx.x; i < DH * WS / 4; i += 256) w2s4[i] = W24[i];
    __syncthreads();

    float* wdecF = (float*)g_wdec;        // [k][j][16] floats
    int t = threadIdx.x;
    if (t < 144) {
        int d = t / WS, o = t - (t / WS) * WS;
        const float4* w14 = (const float4*)(dec_W1 + ((size_t)k * WS + d) * DH);
        float a0 = 0.f, a1 = 0.f, a2 = 0.f, a3 = 0.f;
        float a4 = 0.f, a5 = 0.f, a6 = 0.f, a7 = 0.f;
        for (int q = 0; q < DH / 4; q += 2) {
            float4 u = w14[q], v = w14[q + 1];
            int h = q * 4;
            a0 = fmaf(u.x, w2s[(h + 0) * WS + o], a0);
            a1 = fmaf(u.y, w2s[(h + 1) * WS + o], a1);
            a2 = fmaf(u.z, w2s[(h + 2) * WS + o], a2);
            a3 = fmaf(u.w, w2s[(h + 3) * WS + o], a3);
            a4 = fmaf(v.x, w2s[(h + 4) * WS + o], a4);
            a5 = fmaf(v.y, w2s[(h + 5) * WS + o], a5);
            a6 = fmaf(v.z, w2s[(h + 6) * WS + o], a6);
            a7 = fmaf(v.w, w2s[(h + 7) * WS + o], a7);
        }
        // transposed: row = (k, out=o), element d
        wdecF[((size_t)k * WS + o) * 16 + d] =
            ((a0 + a1) + (a2 + a3)) + ((a4 + a5) + (a6 + a7));
    } else if (t < 156) {
        int o = t - 144;
        const float4* b14 = (const float4*)(dec_b1 + (size_t)k * DH);
        float a0 = dec_b2[k * WS + o], a1 = 0.f, a2 = 0.f, a3 = 0.f;
        for (int q = 0; q < DH / 4; ++q) {
            float4 u = b14[q];
            int h = q * 4;
            a0 = fmaf(u.x, w2s[(h + 0) * WS + o], a0);
            a1 = fmaf(u.y, w2s[(h + 1) * WS + o], a1);
            a2 = fmaf(u.z, w2s[(h + 2) * WS + o], a2);
            a3 = fmaf(u.w, w2s[(h + 3) * WS + o], a3);
        }
        wdecF[((size_t)k * WS + o) * 16 + 12] = (a0 + a1) + (a2 + a3);
    }
}

// ---------------------------------------------------------------------------
// Kernel 3: recurrence + fused decoder. One row per 16-lane group (shfl
// broadcast). Prescaled EX2/RCP activations. gi: 4-deep rotating prefetch.
// Decoder weights live in dynamic smem (LDS.128, off critical path).
// ---------------------------------------------------------------------------
__device__ __forceinline__ void bcast(float h, float* hx) {
#pragma unroll
    for (int i = 0; i < 12; ++i) hx[i] = __shfl_sync(0xffffffffu, h, i, 16);
}

__device__ __forceinline__ float gates(const float* hx, float gr, float gz,
                                       float gn, float bnp,
                                       const float* wr, const float* wz,
                                       const float* wn, float h) {
    float a0 = gr, a1 = 0.f, b0 = gz, b1 = 0.f, c0 = bnp, c1 = 0.f;
#pragma unroll
    for (int i = 0; i < 12; i += 2) {
        a0 = fmaf(wr[i], hx[i], a0); a1 = fmaf(wr[i + 1], hx[i + 1], a1);
        b0 = fmaf(wz[i], hx[i], b0); b1 = fmaf(wz[i + 1], hx[i + 1], b1);
        c0 = fmaf(wn[i], hx[i], c0); c1 = fmaf(wn[i + 1], hx[i + 1], c1);
    }
    float r = frcp(1.0f + fex2(a0 + a1));              // sigmoid (prescaled)
    float z = frcp(1.0f + fex2(b0 + b1));
    float n = fmaf(2.0f, frcp(1.0f + fex2(fmaf(r, c0 + c1, gn))), -1.0f);
    return fmaf(z, h - n, n);
}

__device__ __forceinline__ float decacc(const float* hx, const float4* wb) {
    float4 w0 = wb[0], w1 = wb[1], w2 = wb[2];
    float be = wb[3].x;
    float s0 = be, s1 = 0.f, s2 = 0.f, s3 = 0.f;
    s0 = fmaf(hx[0], w0.x, s0); s1 = fmaf(hx[1], w0.y, s1);
    s2 = fmaf(hx[2], w0.z, s2); s3 = fmaf(hx[3], w0.w, s3);
    s0 = fmaf(hx[4], w1.x, s0); s1 = fmaf(hx[5], w1.y, s1);
    s2 = fmaf(hx[6], w1.z, s2); s3 = fmaf(hx[7], w1.w, s3);
    s0 = fmaf(hx[8], w2.x, s0); s1 = fmaf(hx[9], w2.y, s1);
    s2 = fmaf(hx[10], w2.z, s2); s3 = fmaf(hx[11], w2.w, s3);
    return (s0 + s1) + (s2 + s3);
}

extern __shared__ float4 s_dyn[];   // [0..1919]: pegis, [1920..9599]: wdec

__global__ void __launch_bounds__(128) rnn_kernel(const float* __restrict__ Whh,
                                                  const float* __restrict__ bhh,
                                                  float* __restrict__ out) {
    float4* pegis = s_dyn;                     // Kseg*WS  (30 KB)
    float4* wsm   = s_dyn + Kseg * WS;         // Kseg*WS*4 (120 KB)
    int lane16 = threadIdx.x & 15;
    int row = blockIdx.x * 8 + (threadIdx.x >> 4);   // 0..1023
    bool act = (lane16 < WS);
    int j = act ? lane16 : (WS - 1);

    float wr[12], wz[12], wn[12];
#pragma unroll
    for (int i = 0; i < 12; ++i) {
        wr[i] = -SCL1 * Whh[j * 12 + i];
        wz[i] = -SCL1 * Whh[(12 + j) * 12 + i];
        wn[i] = -SCL2 * Whh[(24 + j) * 12 + i];
    }
    float bnp = -SCL2 * bhh[24 + j];

    for (int i = threadIdx.x; i < Kseg * WS; i += 128) pegis[i] = g_pegi4[i];
    for (int i = threadIdx.x; i < Kseg * WS * 4; i += 128) wsm[i] = g_wdec[i];
    __syncthreads();

    const float4* pA = g_gi + (size_t)row * WS + j;
    float h = 0.0f;
    float4 a0, a1, a2, a3;
    const float4* q;

    // ---------------- phase 1: first GRU (keep only final h) ---------------
    a0 = pA[0];
    a1 = pA[STR4];
    a2 = pA[2 * STR4];
    a3 = pA[3 * STR4];
    q = pA + 4 * STR4;
    for (int t = 0; t < Kseg; t += 4) {
        float hx[12];
        bcast(h, hx); h = gates(hx, a0.x, a0.y, a0.z, bnp, wr, wz, wn, h);
        a0 = q[0];
        bcast(h, hx); h = gates(hx, a1.x, a1.y, a1.z, bnp, wr, wz, wn, h);
        a1 = q[STR4];
        bcast(h, hx); h = gates(hx, a2.x, a2.y, a2.z, bnp, wr, wz, wn, h);
        a2 = q[2 * STR4];
        bcast(h, hx); h = gates(hx, a3.x, a3.y, a3.z, bnp, wr, wz, wn, h);
        a3 = q[3 * STR4];
        q += 4 * STR4;
    }

    // ---------------- phase 2: second GRU + fused decoder -------------------
    float* outp = out + (size_t)row * 1920 + j;
    const float4* wj = wsm + (size_t)j * 4;    // + t*48 per step

    a0 = pA[0];
    a1 = pA[STR4];
    a2 = pA[2 * STR4];
    a3 = pA[3 * STR4];
    q = pA + 4 * STR4;
    const float4* pg = pegis + j;

#define STEP2(AREG, PV, TT, QOFF)                                           \
    {                                                                       \
        float hx[12];                                                       \
        bcast(h, hx);                                                       \
        if (act && (TT) > 0) {                                              \
            float oa = decacc(hx, wj + (size_t)((TT) - 1) * 48);            \
            outp[((TT) - 1) * 12] = oa;                                     \
        }                                                                   \
        h = gates(hx, AREG.x + PV.x, AREG.y + PV.y, AREG.z + PV.z, bnp,     \
                  wr, wz, wn, h);                                           \
        AREG = q[QOFF];                                                     \
    }

    for (int t = 0; t < Kseg; t += 4) {
        float4 p0 = pg[0], p1 = pg[WS], p2 = pg[2 * WS], p3 = pg[3 * WS];
        pg += 4 * WS;
        STEP2(a0, p0, t + 0, 0);
        STEP2(a1, p1, t + 1, STR4);
        STEP2(a2, p2, t + 2, 2 * STR4);
        STEP2(a3, p3, t + 3, 3 * STR4);
        q += 4 * STR4;
    }
#undef STEP2

    // tail: out for t = Kseg-1
    {
        float hx[12];
        bcast(h, hx);
        if (act) {
            float oa = decacc(hx, wj + (size_t)(Kseg - 1) * 48);
            outp[(Kseg - 1) * 12] = oa;
        }
    }
}

// ---------------------------------------------------------------------------
extern "C" void kernel_launch(void* const* d_in, const int* in_sizes, int n_in,
                              void* d_out, int out_size) {
    const float* x     = (const float*)d_in[0];
    const float* enc_W = (const float*)d_in[1];
    const float* enc_b = (const float*)d_in[2];
    const float* Wih   = (const float*)d_in[3];
    const float* Whh   = (const float*)d_in[4];
    const float* bih   = (const float*)d_in[5];
    const float* bhh   = (const float*)d_in[6];
    const float* dW1   = (const float*)d_in[7];
    const float* db1   = (const float*)d_in[8];
    const float* dW2   = (const float*)d_in[9];
    const float* db2   = (const float*)d_in[10];
    float* out = (float*)d_out;

    const int RNN_SMEM = Kseg * WS * 5 * 16;   // 153600 B
    cudaFuncSetAttribute(rnn_kernel,
                         cudaFuncAttributeMaxDynamicSharedMemorySize,
                         RNN_SMEM);

    enc_gi_kernel<<<640, 256>>>(x, enc_W, enc_b, Wih, bih, bhh);
    weff_pegi_kernel<<<Kseg + 1, 256>>>(dW1, db1, dW2, db2, Wih);
    rnn_kernel<<<128, 128, RNN_SMEM>>>(Whh, bhh, out);
}